// round 1
// baseline (speedup 1.0000x reference)
#include <cuda_runtime.h>

// Problem constants
#define TT     25
#define FF     14
#define HH     24
#define GG     96      // 4*H
#define NSTEPS 13      // WINDOW_HALF + 1 : fwd needs t=0..12, bwd needs t=24..12
#define BTOT   65536
#define BLK    128

// Scratch: center vectors [B][2H]  (fwd writes [0:24), bwd writes [24:48))
__device__ float g_center[(size_t)BTOT * 2 * HH];

// ---- fast, accurate activations (EX2/RCP: ~2 ulp, far inside 1e-3 budget) ----
__device__ __forceinline__ float ex2f_(float x) {
    float y; asm("ex2.approx.f32 %0, %1;" : "=f"(y) : "f"(x)); return y;
}
__device__ __forceinline__ float rcpf_(float x) {
    float y; asm("rcp.approx.f32 %0, %1;" : "=f"(y) : "f"(x)); return y;
}
__device__ __forceinline__ float sigf_(float x) {
    // 1/(1+exp(-x)) ; exp(-x) = 2^(-x*log2(e)); inf-safe (rcp(inf)=0)
    return rcpf_(1.0f + ex2f_(-1.4426950408889634f * x));
}
__device__ __forceinline__ float tanhf_(float x) {
    // tanh(x) = (a-1)/(a+1), a = exp(2x); clamp avoids inf*0=NaN
    x = fminf(fmaxf(x, -30.0f), 30.0f);
    float a = ex2f_(2.8853900817779268f * x);
    return (a - 1.0f) * rcpf_(a + 1.0f);
}

__global__ __launch_bounds__(BLK)
void lstm_kernel(const float* __restrict__ x,
                 const float* __restrict__ wih_f, const float* __restrict__ whh_f,
                 const float* __restrict__ bih_f, const float* __restrict__ bhh_f,
                 const float* __restrict__ wih_b, const float* __restrict__ whh_b,
                 const float* __restrict__ bih_b, const float* __restrict__ bhh_b)
{
    __shared__ float s_wih[GG * FF];     //  5376 B
    __shared__ float s_whh[GG * HH];     //  9216 B
    __shared__ float s_b[GG];            //   384 B  (b_ih + b_hh fused)
    __shared__ float s_c [BLK * 25];     // 12800 B  (pad 25: conflict-free)
    __shared__ float s_hn[BLK * 25];     // 12800 B

    const int dir = blockIdx.x & 1;
    const float* wih = dir ? wih_b : wih_f;
    const float* whh = dir ? whh_b : whh_f;
    const float* bih = dir ? bih_b : bih_f;
    const float* bhh = dir ? bhh_b : bhh_f;

    for (int i = threadIdx.x; i < GG * FF; i += BLK) s_wih[i] = wih[i];
    for (int i = threadIdx.x; i < GG * HH; i += BLK) s_whh[i] = whh[i];
    if (threadIdx.x < GG) s_b[threadIdx.x] = bih[threadIdx.x] + bhh[threadIdx.x];
    __syncthreads();

    const int b = (blockIdx.x >> 1) * BLK + threadIdx.x;   // exact cover of [0,65536)

    float h[HH];
    float* cme  = &s_c [threadIdx.x * 25];
    float* hnme = &s_hn[threadIdx.x * 25];
    #pragma unroll
    for (int j = 0; j < HH; j++) { h[j] = 0.0f; cme[j] = 0.0f; }

    const float* xb = x + (size_t)b * (TT * FF);
    const int t0 = dir ? (TT - 1) : 0;
    const int dt = dir ? -1 : 1;

    for (int s = 0; s < NSTEPS; ++s) {
        const float* xt = xb + (t0 + dt * s) * FF;   // 8B-aligned (14 floats/row)
        float xv[FF];
        #pragma unroll
        for (int k = 0; k < FF / 2; ++k) {
            float2 v = __ldg((const float2*)xt + k);
            xv[2 * k] = v.x; xv[2 * k + 1] = v.y;
        }

        #pragma unroll 2
        for (int j = 0; j < HH; ++j) {
            float ai = s_b[j], af = s_b[j + HH], ag = s_b[j + 2 * HH], ao = s_b[j + 3 * HH];
            const float* wi = &s_wih[j * FF];
            const float* wr = &s_whh[j * HH];
            #pragma unroll
            for (int k = 0; k < FF; ++k) {
                float xk = xv[k];
                ai += xk * wi[k];
                af += xk * wi[HH * FF + k];
                ag += xk * wi[2 * HH * FF + k];
                ao += xk * wi[3 * HH * FF + k];
            }
            #pragma unroll
            for (int k = 0; k < HH; ++k) {
                float hk = h[k];
                ai += hk * wr[k];
                af += hk * wr[HH * HH + k];
                ag += hk * wr[2 * HH * HH + k];
                ao += hk * wr[3 * HH * HH + k];
            }
            float ii = sigf_(ai), ff = sigf_(af), oo = sigf_(ao), gg = tanhf_(ag);
            float cn = ff * cme[j] + ii * gg;
            cme[j]  = cn;
            hnme[j] = oo * tanhf_(cn);
        }
        #pragma unroll
        for (int j = 0; j < HH; ++j) h[j] = hnme[j];   // private smem, no sync needed
    }

    float* outp = g_center + (size_t)b * (2 * HH) + dir * HH;
    #pragma unroll
    for (int j = 0; j < HH; ++j) outp[j] = h[j];
}

__global__ __launch_bounds__(256)
void head_kernel(const float* __restrict__ head_w, const float* __restrict__ head_b,
                 float* __restrict__ out)
{
    __shared__ float s_w[4 * 48];
    __shared__ float s_bb[4];
    if (threadIdx.x < 192) s_w[threadIdx.x] = head_w[threadIdx.x];
    if (threadIdx.x < 4)   s_bb[threadIdx.x] = head_b[threadIdx.x];
    __syncthreads();

    const int b = blockIdx.x * blockDim.x + threadIdx.x;
    const float* ctr = g_center + (size_t)b * 48;
    float a0 = s_bb[0], a1 = s_bb[1], a2 = s_bb[2], a3 = s_bb[3];
    #pragma unroll
    for (int k = 0; k < 48; ++k) {
        float v = ctr[k];
        a0 += v * s_w[k];
        a1 += v * s_w[48 + k];
        a2 += v * s_w[96 + k];
        a3 += v * s_w[144 + k];
    }
    ((float4*)out)[b] = make_float4(a0, a1, a2, a3);
}

extern "C" void kernel_launch(void* const* d_in, const int* in_sizes, int n_in,
                              void* d_out, int out_size)
{
    const float* x      = (const float*)d_in[0];
    const float* wih_f  = (const float*)d_in[1];
    const float* whh_f  = (const float*)d_in[2];
    const float* bih_f  = (const float*)d_in[3];
    const float* bhh_f  = (const float*)d_in[4];
    const float* wih_b  = (const float*)d_in[5];
    const float* whh_b  = (const float*)d_in[6];
    const float* bih_b  = (const float*)d_in[7];
    const float* bhh_b  = (const float*)d_in[8];
    const float* head_w = (const float*)d_in[9];
    const float* head_b = (const float*)d_in[10];
    float* out = (float*)d_out;

    // 2 directions * 512 b-blocks of 128 threads = exact cover
    lstm_kernel<<<(BTOT / BLK) * 2, BLK>>>(x, wih_f, whh_f, bih_f, bhh_f,
                                           wih_b, whh_b, bih_b, bhh_b);
    head_kernel<<<BTOT / 256, 256>>>(head_w, head_b, out);
}

// round 2
// speedup vs baseline: 1.0770x; 1.0770x over previous
#include <cuda_runtime.h>

// Problem constants
#define TT     25
#define FF     14
#define HH     24
#define NSTEPS 13      // WINDOW_HALF + 1 : fwd needs t=0..12, bwd needs t=24..12
#define BTOT   65536
#define BLK    128

typedef unsigned long long u64;

// Scratch: center vectors [B][2H]  (fwd writes [0:24), bwd writes [24:48))
__device__ float g_center[(size_t)BTOT * 2 * HH];

// ---- packed f32x2 helpers (Blackwell) ----
__device__ __forceinline__ u64 pack2(float lo, float hi) {
    u64 r; asm("mov.b64 %0, {%1, %2};" : "=l"(r) : "f"(lo), "f"(hi)); return r;
}
__device__ __forceinline__ void unpack2(u64 v, float& lo, float& hi) {
    asm("mov.b64 {%0, %1}, %2;" : "=f"(lo), "=f"(hi) : "l"(v));
}
__device__ __forceinline__ void ffma2(u64& d, u64 a, u64 b) {
    asm("fma.rn.f32x2 %0, %1, %2, %0;" : "+l"(d) : "l"(a), "l"(b));
}

// ---- fast, accurate activations (EX2/RCP: ~2 ulp, far inside 1e-3 budget) ----
__device__ __forceinline__ float ex2f_(float x) {
    float y; asm("ex2.approx.f32 %0, %1;" : "=f"(y) : "f"(x)); return y;
}
__device__ __forceinline__ float rcpf_(float x) {
    float y; asm("rcp.approx.f32 %0, %1;" : "=f"(y) : "f"(x)); return y;
}
__device__ __forceinline__ float sigf_(float x) {
    return rcpf_(1.0f + ex2f_(-1.4426950408889634f * x));
}
__device__ __forceinline__ float tanhf_(float x) {
    x = fminf(fmaxf(x, -30.0f), 30.0f);
    float a = ex2f_(2.8853900817779268f * x);
    return (a - 1.0f) * rcpf_(a + 1.0f);
}

__global__ __launch_bounds__(BLK)
void lstm_kernel(const float* __restrict__ x,
                 const float* __restrict__ wih_f, const float* __restrict__ whh_f,
                 const float* __restrict__ bih_f, const float* __restrict__ bhh_f,
                 const float* __restrict__ wih_b, const float* __restrict__ whh_b,
                 const float* __restrict__ bih_b, const float* __restrict__ bhh_b)
{
    // Gate-pair packed weights: [unit j][k] -> (gate_i, gate_f) and (gate_g, gate_o)
    __shared__ u64 s_wif[HH * FF];     // 2688 B
    __shared__ u64 s_wgo[HH * FF];     // 2688 B
    __shared__ u64 s_rif[HH * HH];     // 4608 B
    __shared__ u64 s_rgo[HH * HH];     // 4608 B
    __shared__ u64 s_bif[HH];          //  192 B (b_ih + b_hh fused, packed)
    __shared__ u64 s_bgo[HH];          //  192 B
    __shared__ float s_c[BLK * 25];    // 12800 B (stride 25: conflict-free)
    __shared__ float s_h[BLK * 25];    // 12800 B

    const int dir = blockIdx.x & 1;
    const float* wih = dir ? wih_b : wih_f;
    const float* whh = dir ? whh_b : whh_f;
    const float* bih = dir ? bih_b : bih_f;
    const float* bhh = dir ? bhh_b : bhh_f;

    for (int i = threadIdx.x; i < HH * FF; i += BLK) {
        int j = i / FF, k = i % FF;
        s_wif[i] = pack2(wih[j * FF + k],            wih[(j + HH) * FF + k]);
        s_wgo[i] = pack2(wih[(j + 2 * HH) * FF + k], wih[(j + 3 * HH) * FF + k]);
    }
    for (int i = threadIdx.x; i < HH * HH; i += BLK) {
        int j = i / HH, k = i % HH;
        s_rif[i] = pack2(whh[j * HH + k],            whh[(j + HH) * HH + k]);
        s_rgo[i] = pack2(whh[(j + 2 * HH) * HH + k], whh[(j + 3 * HH) * HH + k]);
    }
    if (threadIdx.x < HH) {
        int j = threadIdx.x;
        s_bif[j] = pack2(bih[j] + bhh[j],                   bih[j + HH] + bhh[j + HH]);
        s_bgo[j] = pack2(bih[j + 2 * HH] + bhh[j + 2 * HH], bih[j + 3 * HH] + bhh[j + 3 * HH]);
    }
    __syncthreads();

    const int b = (blockIdx.x >> 1) * BLK + threadIdx.x;   // exact cover of [0,65536)

    u64 h2[HH];                                  // h duplicated into both f32x2 lanes
    float* cme = &s_c[threadIdx.x * 25];
    float* hme = &s_h[threadIdx.x * 25];
    #pragma unroll
    for (int j = 0; j < HH; j++) { h2[j] = 0ULL; cme[j] = 0.0f; }

    const float* xb = x + (size_t)b * (TT * FF);
    const int t0 = dir ? (TT - 1) : 0;
    const int dt = dir ? -1 : 1;

    for (int s = 0; s < NSTEPS; ++s) {
        const float* xt = xb + (t0 + dt * s) * FF;   // 8B-aligned (14 floats/row)
        u64 xv2[FF];
        #pragma unroll
        for (int k = 0; k < FF / 2; ++k) {
            float2 v = __ldg((const float2*)xt + k);
            xv2[2 * k]     = pack2(v.x, v.x);
            xv2[2 * k + 1] = pack2(v.y, v.y);
        }

        #pragma unroll 1
        for (int j = 0; j < HH; ++j) {
            u64 aif = s_bif[j];
            u64 ago = s_bgo[j];
            const u64* wif = &s_wif[j * FF];
            const u64* wgo = &s_wgo[j * FF];
            const u64* rif = &s_rif[j * HH];
            const u64* rgo = &s_rgo[j * HH];
            #pragma unroll
            for (int k = 0; k < FF; ++k) {
                ffma2(aif, xv2[k], wif[k]);
                ffma2(ago, xv2[k], wgo[k]);
            }
            #pragma unroll
            for (int k = 0; k < HH; ++k) {
                ffma2(aif, h2[k], rif[k]);
                ffma2(ago, h2[k], rgo[k]);
            }
            float ai, af, ag, ao;
            unpack2(aif, ai, af);
            unpack2(ago, ag, ao);
            float ii = sigf_(ai), ff = sigf_(af), oo = sigf_(ao), gg = tanhf_(ag);
            float cn = ff * cme[j] + ii * gg;
            cme[j] = cn;
            hme[j] = oo * tanhf_(cn);
        }
        #pragma unroll
        for (int j = 0; j < HH; ++j) {           // private smem rows, no sync needed
            float hv = hme[j];
            h2[j] = pack2(hv, hv);
        }
    }

    float* outp = g_center + (size_t)b * (2 * HH) + dir * HH;
    #pragma unroll
    for (int j = 0; j < HH; ++j) {
        float lo, hi; unpack2(h2[j], lo, hi);
        outp[j] = lo;
    }
}

__global__ __launch_bounds__(256)
void head_kernel(const float* __restrict__ head_w, const float* __restrict__ head_b,
                 float* __restrict__ out)
{
    __shared__ float s_w[4 * 48];
    __shared__ float s_bb[4];
    if (threadIdx.x < 192) s_w[threadIdx.x] = head_w[threadIdx.x];
    if (threadIdx.x < 4)   s_bb[threadIdx.x] = head_b[threadIdx.x];
    __syncthreads();

    const int b = blockIdx.x * blockDim.x + threadIdx.x;
    const float* ctr = g_center + (size_t)b * 48;
    float a0 = s_bb[0], a1 = s_bb[1], a2 = s_bb[2], a3 = s_bb[3];
    #pragma unroll
    for (int k = 0; k < 48; ++k) {
        float v = ctr[k];
        a0 += v * s_w[k];
        a1 += v * s_w[48 + k];
        a2 += v * s_w[96 + k];
        a3 += v * s_w[144 + k];
    }
    ((float4*)out)[b] = make_float4(a0, a1, a2, a3);
}

extern "C" void kernel_launch(void* const* d_in, const int* in_sizes, int n_in,
                              void* d_out, int out_size)
{
    const float* x      = (const float*)d_in[0];
    const float* wih_f  = (const float*)d_in[1];
    const float* whh_f  = (const float*)d_in[2];
    const float* bih_f  = (const float*)d_in[3];
    const float* bhh_f  = (const float*)d_in[4];
    const float* wih_b  = (const float*)d_in[5];
    const float* whh_b  = (const float*)d_in[6];
    const float* bih_b  = (const float*)d_in[7];
    const float* bhh_b  = (const float*)d_in[8];
    const float* head_w = (const float*)d_in[9];
    const float* head_b = (const float*)d_in[10];
    float* out = (float*)d_out;

    lstm_kernel<<<(BTOT / BLK) * 2, BLK>>>(x, wih_f, whh_f, bih_f, bhh_f,
                                           wih_b, whh_b, bih_b, bhh_b);
    head_kernel<<<BTOT / 256, 256>>>(head_w, head_b, out);
}

// round 3
// speedup vs baseline: 1.1364x; 1.0551x over previous
#include <cuda_runtime.h>

// Problem constants
#define TT     25
#define FF     14
#define HH     24
#define KK     38     // FF + HH fused weight row
#define NSTEPS 13     // WINDOW_HALF + 1 : fwd needs t=0..12, bwd needs t=24..12
#define BTOT   65536
#define BLK    128
#define NCLS   4

typedef unsigned long long u64;

// ---- packed f32x2 helpers (Blackwell) ----
__device__ __forceinline__ u64 pack2(float lo, float hi) {
    u64 r; asm("mov.b64 %0, {%1, %2};" : "=l"(r) : "f"(lo), "f"(hi)); return r;
}
__device__ __forceinline__ float lo2(u64 v) {
    float lo, hi; asm("mov.b64 {%0, %1}, %2;" : "=f"(lo), "=f"(hi) : "l"(v)); return lo;
}
__device__ __forceinline__ void unpack2(u64 v, float& lo, float& hi) {
    asm("mov.b64 {%0, %1}, %2;" : "=f"(lo), "=f"(hi) : "l"(v));
}
__device__ __forceinline__ void ffma2(u64& d, u64 a, u64 b) {
    asm("fma.rn.f32x2 %0, %1, %2, %0;" : "+l"(d) : "l"(a), "l"(b));
}

// ---- fast, accurate activations (EX2/RCP: ~2 ulp, far inside 1e-3 budget) ----
__device__ __forceinline__ float ex2f_(float x) {
    float y; asm("ex2.approx.f32 %0, %1;" : "=f"(y) : "f"(x)); return y;
}
__device__ __forceinline__ float rcpf_(float x) {
    float y; asm("rcp.approx.f32 %0, %1;" : "=f"(y) : "f"(x)); return y;
}
__device__ __forceinline__ float sigf_(float x) {
    return rcpf_(1.0f + ex2f_(-1.4426950408889634f * x));
}
__device__ __forceinline__ float tanhf_(float x) {
    x = fminf(fmaxf(x, -30.0f), 30.0f);
    float a = ex2f_(2.8853900817779268f * x);
    return (a - 1.0f) * rcpf_(a + 1.0f);
}

__global__ __launch_bounds__(256)
void init_out_kernel(const float* __restrict__ head_b, float* __restrict__ out)
{
    const int b = blockIdx.x * blockDim.x + threadIdx.x;
    ((float4*)out)[b] = make_float4(head_b[0], head_b[1], head_b[2], head_b[3]);
}

__global__ __launch_bounds__(BLK)
void lstm_kernel(const float* __restrict__ x,
                 const float* __restrict__ wih_f, const float* __restrict__ whh_f,
                 const float* __restrict__ bih_f, const float* __restrict__ bhh_f,
                 const float* __restrict__ wih_b, const float* __restrict__ whh_b,
                 const float* __restrict__ bih_b, const float* __restrict__ bhh_b,
                 const float* __restrict__ head_w, float* __restrict__ out)
{
    // One 16B entry per (unit j, k): {(w_i,w_f),(w_g,w_o)} ; rows fuse x(14)+h(24)
    __shared__ ulonglong2 s_w[HH * KK];   // 14592 B
    __shared__ u64 s_bif[HH];             //   192 B (b_ih + b_hh fused, gate-paired)
    __shared__ u64 s_bgo[HH];             //   192 B
    __shared__ float s_c[BLK * 25];       // 12800 B (stride 25: conflict-free)
    __shared__ float s_h[BLK * 25];       // 12800 B
    __shared__ float s_hw[NCLS * HH];     //   384 B (head slice for this direction)

    const int dir = blockIdx.x & 1;
    const float* wih = dir ? wih_b : wih_f;
    const float* whh = dir ? whh_b : whh_f;
    const float* bih = dir ? bih_b : bih_f;
    const float* bhh = dir ? bhh_b : bhh_f;

    for (int i = threadIdx.x; i < HH * KK; i += BLK) {
        int j = i / KK, k = i % KK;
        float wi, wf, wg, wo;
        if (k < FF) {
            wi = wih[j * FF + k];
            wf = wih[(j + HH) * FF + k];
            wg = wih[(j + 2 * HH) * FF + k];
            wo = wih[(j + 3 * HH) * FF + k];
        } else {
            int kk = k - FF;
            wi = whh[j * HH + kk];
            wf = whh[(j + HH) * HH + kk];
            wg = whh[(j + 2 * HH) * HH + kk];
            wo = whh[(j + 3 * HH) * HH + kk];
        }
        ulonglong2 w; w.x = pack2(wi, wf); w.y = pack2(wg, wo);
        s_w[i] = w;
    }
    if (threadIdx.x < HH) {
        int j = threadIdx.x;
        s_bif[j] = pack2(bih[j] + bhh[j],                   bih[j + HH] + bhh[j + HH]);
        s_bgo[j] = pack2(bih[j + 2 * HH] + bhh[j + 2 * HH], bih[j + 3 * HH] + bhh[j + 3 * HH]);
    }
    if (threadIdx.x < NCLS * HH) {
        int m = threadIdx.x / HH, j = threadIdx.x % HH;
        s_hw[m * HH + j] = head_w[m * (2 * HH) + dir * HH + j];
    }
    __syncthreads();

    const int b = (blockIdx.x >> 1) * BLK + threadIdx.x;   // exact cover of [0,65536)

    u64 h2[HH];                                  // h duplicated into both f32x2 lanes
    float* cme = &s_c[threadIdx.x * 25];
    float* hme = &s_h[threadIdx.x * 25];
    #pragma unroll
    for (int j = 0; j < HH; j++) { h2[j] = 0ULL; cme[j] = 0.0f; }

    const float* xb = x + (size_t)b * (TT * FF);
    const int t0 = dir ? (TT - 1) : 0;
    const int dt = dir ? -1 : 1;

    for (int s = 0; s < NSTEPS; ++s) {
        const float* xt = xb + (t0 + dt * s) * FF;   // 8B-aligned (14 floats/row)
        u64 xv2[FF];
        #pragma unroll
        for (int k = 0; k < FF / 2; ++k) {
            float2 v = __ldg((const float2*)xt + k);
            xv2[2 * k]     = pack2(v.x, v.x);
            xv2[2 * k + 1] = pack2(v.y, v.y);
        }

        #pragma unroll 1
        for (int j = 0; j < HH; ++j) {
            u64 aif = s_bif[j];
            u64 ago = s_bgo[j];
            const ulonglong2* wp = &s_w[j * KK];
            #pragma unroll
            for (int k = 0; k < FF; ++k) {
                ulonglong2 w = wp[k];                 // one broadcast LDS.128
                ffma2(aif, xv2[k], w.x);
                ffma2(ago, xv2[k], w.y);
            }
            #pragma unroll
            for (int k = 0; k < HH; ++k) {
                ulonglong2 w = wp[FF + k];            // one broadcast LDS.128
                ffma2(aif, h2[k], w.x);
                ffma2(ago, h2[k], w.y);
            }
            float ai, af, ag, ao;
            unpack2(aif, ai, af);
            unpack2(ago, ag, ao);
            float ii = sigf_(ai), ff = sigf_(af), oo = sigf_(ao), gg = tanhf_(ag);
            float cn = ff * cme[j] + ii * gg;
            cme[j] = cn;
            hme[j] = oo * tanhf_(cn);
        }
        #pragma unroll
        for (int j = 0; j < HH; ++j) {           // private smem rows, no sync needed
            float hv = hme[j];
            h2[j] = pack2(hv, hv);
        }
    }

    // Fused head: this direction's partial logits, atomically accumulated.
    float p0 = 0.f, p1 = 0.f, p2 = 0.f, p3 = 0.f;
    #pragma unroll
    for (int j = 0; j < HH; ++j) {
        float hv = lo2(h2[j]);
        p0 += hv * s_hw[j];
        p1 += hv * s_hw[HH + j];
        p2 += hv * s_hw[2 * HH + j];
        p3 += hv * s_hw[3 * HH + j];
    }
    float* ob = out + (size_t)b * NCLS;
    atomicAdd(ob + 0, p0);
    atomicAdd(ob + 1, p1);
    atomicAdd(ob + 2, p2);
    atomicAdd(ob + 3, p3);
}

extern "C" void kernel_launch(void* const* d_in, const int* in_sizes, int n_in,
                              void* d_out, int out_size)
{
    const float* x      = (const float*)d_in[0];
    const float* wih_f  = (const float*)d_in[1];
    const float* whh_f  = (const float*)d_in[2];
    const float* bih_f  = (const float*)d_in[3];
    const float* bhh_f  = (const float*)d_in[4];
    const float* wih_b  = (const float*)d_in[5];
    const float* whh_b  = (const float*)d_in[6];
    const float* bih_b  = (const float*)d_in[7];
    const float* bhh_b  = (const float*)d_in[8];
    const float* head_w = (const float*)d_in[9];
    const float* head_b = (const float*)d_in[10];
    float* out = (float*)d_out;

    init_out_kernel<<<BTOT / 256, 256>>>(head_b, out);
    lstm_kernel<<<(BTOT / BLK) * 2, BLK>>>(x, wih_f, whh_f, bih_f, bhh_f,
                                           wih_b, whh_b, bih_b, bhh_b,
                                           head_w, out);
}

// round 4
// speedup vs baseline: 1.1678x; 1.0277x over previous
#include <cuda_runtime.h>

// Problem constants
#define TT     25
#define FF     14
#define HH     24
#define KK     38     // FF + HH fused weight row
#define NSTEPS 13     // WINDOW_HALF + 1 : fwd needs t=0..12, bwd needs t=24..12
#define BTOT   65536
#define BLK    64
#define NCLS   4

typedef unsigned long long u64;

// ---- packed f32x2 helpers (Blackwell) ----
__device__ __forceinline__ u64 pack2(float lo, float hi) {
    u64 r; asm("mov.b64 %0, {%1, %2};" : "=l"(r) : "f"(lo), "f"(hi)); return r;
}
__device__ __forceinline__ u64 dup2(float v) {
    u64 r; asm("mov.b64 %0, {%1, %1};" : "=l"(r) : "f"(v)); return r;
}
__device__ __forceinline__ void unpack2(u64 v, float& lo, float& hi) {
    asm("mov.b64 {%0, %1}, %2;" : "=f"(lo), "=f"(hi) : "l"(v));
}
__device__ __forceinline__ void ffma2(u64& d, u64 a, u64 b) {
    asm("fma.rn.f32x2 %0, %1, %2, %0;" : "+l"(d) : "l"(a), "l"(b));
}

// ---- fast, accurate activations (EX2/RCP: ~2 ulp, far inside 1e-3 budget) ----
__device__ __forceinline__ float ex2f_(float x) {
    float y; asm("ex2.approx.f32 %0, %1;" : "=f"(y) : "f"(x)); return y;
}
__device__ __forceinline__ float rcpf_(float x) {
    float y; asm("rcp.approx.f32 %0, %1;" : "=f"(y) : "f"(x)); return y;
}
__device__ __forceinline__ float sigf_(float x) {
    return rcpf_(1.0f + ex2f_(-1.4426950408889634f * x));
}
__device__ __forceinline__ float tanhf_(float x) {
    x = fminf(fmaxf(x, -30.0f), 30.0f);
    float a = ex2f_(2.8853900817779268f * x);
    return (a - 1.0f) * rcpf_(a + 1.0f);
}

__global__ __launch_bounds__(256)
void init_out_kernel(const float* __restrict__ head_b, float* __restrict__ out)
{
    const int b = blockIdx.x * blockDim.x + threadIdx.x;
    ((float4*)out)[b] = make_float4(head_b[0], head_b[1], head_b[2], head_b[3]);
}

__global__ __launch_bounds__(BLK)
void lstm_kernel(const float* __restrict__ x,
                 const float* __restrict__ wih_f, const float* __restrict__ whh_f,
                 const float* __restrict__ bih_f, const float* __restrict__ bhh_f,
                 const float* __restrict__ wih_b, const float* __restrict__ whh_b,
                 const float* __restrict__ bih_b, const float* __restrict__ bhh_b,
                 const float* __restrict__ head_w, float* __restrict__ out)
{
    // One 16B entry per (unit j, k): {(w_i,w_f),(w_g,w_o)} ; rows fuse x(14)+h(24)
    __shared__ ulonglong2 s_w[HH * KK];     // 14592 B
    __shared__ u64 s_bif[HH];               //   192 B
    __shared__ u64 s_bgo[HH];               //   192 B
    __shared__ float s_c [2 * BLK * 25];    // 12800 B  (elem0 rows, then elem1 rows)
    __shared__ float s_hn[2 * BLK * 25];    // 12800 B  (new-h staging)
    __shared__ float s_hw[NCLS * HH];       //   384 B

    const int dir = blockIdx.x & 1;
    const float* wih = dir ? wih_b : wih_f;
    const float* whh = dir ? whh_b : whh_f;
    const float* bih = dir ? bih_b : bih_f;
    const float* bhh = dir ? bhh_b : bhh_f;

    for (int i = threadIdx.x; i < HH * KK; i += BLK) {
        int j = i / KK, k = i % KK;
        float wi, wf, wg, wo;
        if (k < FF) {
            wi = wih[j * FF + k];
            wf = wih[(j + HH) * FF + k];
            wg = wih[(j + 2 * HH) * FF + k];
            wo = wih[(j + 3 * HH) * FF + k];
        } else {
            int kk = k - FF;
            wi = whh[j * HH + kk];
            wf = whh[(j + HH) * HH + kk];
            wg = whh[(j + 2 * HH) * HH + kk];
            wo = whh[(j + 3 * HH) * HH + kk];
        }
        ulonglong2 w; w.x = pack2(wi, wf); w.y = pack2(wg, wo);
        s_w[i] = w;
    }
    if (threadIdx.x < HH) {
        int j = threadIdx.x;
        s_bif[j] = pack2(bih[j] + bhh[j],                   bih[j + HH] + bhh[j + HH]);
        s_bgo[j] = pack2(bih[j + 2 * HH] + bhh[j + 2 * HH], bih[j + 3 * HH] + bhh[j + 3 * HH]);
    }
    for (int i = threadIdx.x; i < NCLS * HH; i += BLK) {
        int m = i / HH, j = i % HH;
        s_hw[m * HH + j] = head_w[m * (2 * HH) + dir * HH + j];
    }
    __syncthreads();

    // Two batch elements per thread
    const int b0 = (blockIdx.x >> 1) * (2 * BLK) + threadIdx.x;
    const int b1 = b0 + BLK;

    float h0[HH], h1[HH];
    float* c0 = &s_c [threadIdx.x * 25];
    float* c1 = &s_c [(BLK + threadIdx.x) * 25];
    float* n0 = &s_hn[threadIdx.x * 25];
    float* n1 = &s_hn[(BLK + threadIdx.x) * 25];
    #pragma unroll
    for (int j = 0; j < HH; j++) { h0[j] = 0.f; h1[j] = 0.f; c0[j] = 0.f; c1[j] = 0.f; }

    const float* xb0 = x + (size_t)b0 * (TT * FF);
    const float* xb1 = x + (size_t)b1 * (TT * FF);
    const int t0 = dir ? (TT - 1) : 0;
    const int dt = dir ? -1 : 1;

    for (int s = 0; s < NSTEPS; ++s) {
        const int toff = (t0 + dt * s) * FF;
        float xv0[FF], xv1[FF];
        #pragma unroll
        for (int k = 0; k < FF / 2; ++k) {
            float2 v0 = __ldg((const float2*)(xb0 + toff) + k);
            float2 v1 = __ldg((const float2*)(xb1 + toff) + k);
            xv0[2 * k] = v0.x; xv0[2 * k + 1] = v0.y;
            xv1[2 * k] = v1.x; xv1[2 * k + 1] = v1.y;
        }

        #pragma unroll 1
        for (int j = 0; j < HH; ++j) {
            u64 aif0 = s_bif[j], ago0 = s_bgo[j];
            u64 aif1 = aif0,     ago1 = ago0;
            const ulonglong2* wp = &s_w[j * KK];
            #pragma unroll
            for (int k = 0; k < FF; ++k) {
                ulonglong2 w = wp[k];                 // one broadcast LDS.128, 4 FFMA2
                u64 v0 = dup2(xv0[k]);
                u64 v1 = dup2(xv1[k]);
                ffma2(aif0, v0, w.x); ffma2(ago0, v0, w.y);
                ffma2(aif1, v1, w.x); ffma2(ago1, v1, w.y);
            }
            #pragma unroll
            for (int k = 0; k < HH; ++k) {
                ulonglong2 w = wp[FF + k];
                u64 v0 = dup2(h0[k]);
                u64 v1 = dup2(h1[k]);
                ffma2(aif0, v0, w.x); ffma2(ago0, v0, w.y);
                ffma2(aif1, v1, w.x); ffma2(ago1, v1, w.y);
            }
            {
                float ai, af, ag, ao;
                unpack2(aif0, ai, af); unpack2(ago0, ag, ao);
                float ii = sigf_(ai), ff = sigf_(af), oo = sigf_(ao), gg = tanhf_(ag);
                float cn = ff * c0[j] + ii * gg;
                c0[j] = cn; n0[j] = oo * tanhf_(cn);
            }
            {
                float ai, af, ag, ao;
                unpack2(aif1, ai, af); unpack2(ago1, ag, ao);
                float ii = sigf_(ai), ff = sigf_(af), oo = sigf_(ao), gg = tanhf_(ag);
                float cn = ff * c1[j] + ii * gg;
                c1[j] = cn; n1[j] = oo * tanhf_(cn);
            }
        }
        #pragma unroll
        for (int j = 0; j < HH; ++j) { h0[j] = n0[j]; h1[j] = n1[j]; }  // private rows
    }

    // Fused head: partial logits for this direction, accumulated atomically.
    float p00 = 0.f, p01 = 0.f, p02 = 0.f, p03 = 0.f;
    float p10 = 0.f, p11 = 0.f, p12 = 0.f, p13 = 0.f;
    #pragma unroll
    for (int j = 0; j < HH; ++j) {
        float w0 = s_hw[j], w1 = s_hw[HH + j], w2 = s_hw[2 * HH + j], w3 = s_hw[3 * HH + j];
        p00 += h0[j] * w0; p01 += h0[j] * w1; p02 += h0[j] * w2; p03 += h0[j] * w3;
        p10 += h1[j] * w0; p11 += h1[j] * w1; p12 += h1[j] * w2; p13 += h1[j] * w3;
    }
    float* ob0 = out + (size_t)b0 * NCLS;
    atomicAdd(ob0 + 0, p00); atomicAdd(ob0 + 1, p01);
    atomicAdd(ob0 + 2, p02); atomicAdd(ob0 + 3, p03);
    float* ob1 = out + (size_t)b1 * NCLS;
    atomicAdd(ob1 + 0, p10); atomicAdd(ob1 + 1, p11);
    atomicAdd(ob1 + 2, p12); atomicAdd(ob1 + 3, p13);
}

extern "C" void kernel_launch(void* const* d_in, const int* in_sizes, int n_in,
                              void* d_out, int out_size)
{
    const float* x      = (const float*)d_in[0];
    const float* wih_f  = (const float*)d_in[1];
    const float* whh_f  = (const float*)d_in[2];
    const float* bih_f  = (const float*)d_in[3];
    const float* bhh_f  = (const float*)d_in[4];
    const float* wih_b  = (const float*)d_in[5];
    const float* whh_b  = (const float*)d_in[6];
    const float* bih_b  = (const float*)d_in[7];
    const float* bhh_b  = (const float*)d_in[8];
    const float* head_w = (const float*)d_in[9];
    const float* head_b = (const float*)d_in[10];
    float* out = (float*)d_out;

    init_out_kernel<<<BTOT / 256, 256>>>(head_b, out);
    // 2 dirs * (65536 / (2*BLK)) blocks, each thread does 2 elements
    lstm_kernel<<<(BTOT / (2 * BLK)) * 2, BLK>>>(x, wih_f, whh_f, bih_f, bhh_f,
                                                 wih_b, whh_b, bih_b, bhh_b,
                                                 head_w, out);
}